// round 7
// baseline (speedup 1.0000x reference)
#include <cuda_runtime.h>
#include <cstdint>

#define TT   512
#define BB   128
#define LATN 1024
#define DIMX 256
#define BM   64
#define BN   16
#define BK   64
#define SAR  68      // A-tile [m][k] row stride (multiple of 4 for STS.128)
#define SWR  66      // W-tile [n][k] row stride
#define NT   256

typedef unsigned long long ull;
typedef unsigned u32;

// publish counters: [mi][chunk][part][pad16]
__device__ u32 g_cnt[2][8][4][16];

__device__ __forceinline__ ull fma2(ull a, ull b, ull c) {
    ull d; asm("fma.rn.f32x2 %0, %1, %2, %3;" : "=l"(d) : "l"(a), "l"(b), "l"(c)); return d;
}
__device__ __forceinline__ ull add2(ull a, ull b) {
    ull d; asm("add.rn.f32x2 %0, %1, %2;" : "=l"(d) : "l"(a), "l"(b)); return d;
}
__device__ __forceinline__ float2 unp2(ull v) {
    float2 f; asm("mov.b64 {%0, %1}, %2;" : "=f"(f.x), "=f"(f.y) : "l"(v)); return f;
}
__device__ __forceinline__ u32 ldacq(const u32* p) {
    u32 v; asm volatile("ld.acquire.gpu.u32 %0, [%1];" : "=r"(v) : "l"(p) : "memory"); return v;
}

__global__ void __launch_bounds__(NT, 1)
rnn_persist(const float* __restrict__ x, const float* __restrict__ W,
            const float* __restrict__ b, float* __restrict__ out)
{
    __shared__ float sA[2][BM * SAR];   // 34816 B
    __shared__ float sW[2][BN * SWR];   //  8448 B  (total 43264 B, static)

    const int tid  = threadIdx.x;
    const int cta  = blockIdx.x;
    const int mi   = cta & 1;           // batch half
    const int nj   = cta >> 1;          // N-tile 0..63
    const int m0   = mi * BM;
    const int n0   = nj * BN;
    const int sub  = nj >> 3;           // 128-col h-chunk this CTA produces

    const int lane = tid & 31;
    const int wid  = tid >> 5;          // warp = row-group: rows wid*8 .. wid*8+7
    const int z    = lane & 7;          // k-split class (8-way)
    const int cg   = lane >> 3;         // col quad: cols n0 + 4*cg .. +3

    const int am = tid >> 2;            // A loader row 0..63
    const int aq = tid & 3;             // A loader quad
    const int wk = tid >> 2;            // W loader k row 0..63
    const int wq = tid & 3;             // W loader col quad

    const float4 bias4 = *(const float4*)(b + n0 + 4 * cg);

    long long bud = 1LL << 22;

    float4 va[4], wv;

#define LDG_TILE(kt_, t_)                                                     \
  { const int _kt = (kt_);                                                    \
    wv = *(const float4*)(W + (size_t)(_kt * BK + wk) * LATN + n0 + 4 * wq);  \
    if (_kt < 4) {                                                            \
      const float* _p = x + (size_t)(m0 + am) * (TT * DIMX)                   \
                          + (size_t)(t_) * DIMX + _kt * BK + 4 * aq;          \
      va[0] = __ldcs((const float4*)(_p));                                    \
      va[1] = __ldcs((const float4*)(_p + 16));                               \
      va[2] = __ldcs((const float4*)(_p + 32));                               \
      va[3] = __ldcs((const float4*)(_p + 48));                               \
    } else {                                                                  \
      const float* _p = out + (size_t)((t_) - 1) * (BB * LATN)                \
                            + (size_t)(m0 + am) * LATN + (_kt - 4) * BK + 4 * aq; \
      va[0] = __ldcs((const float4*)(_p));                                    \
      va[1] = __ldcs((const float4*)(_p + 16));                               \
      va[2] = __ldcs((const float4*)(_p + 32));                               \
      va[3] = __ldcs((const float4*)(_p + 48));                               \
    } }

#define STS_TILE(buf_)                                                       \
  { float* _a = &sA[buf_][am * SAR + 4 * aq];                                \
    *(float4*)(_a)      = va[0];                                             \
    *(float4*)(_a + 16) = va[1];                                             \
    *(float4*)(_a + 32) = va[2];                                             \
    *(float4*)(_a + 48) = va[3];                                             \
    float* _w = &sW[buf_][0];                                                \
    _w[(4 * wq + 0) * SWR + wk] = wv.x;                                      \
    _w[(4 * wq + 1) * SWR + wk] = wv.y;                                      \
    _w[(4 * wq + 2) * SWR + wk] = wv.z;                                      \
    _w[(4 * wq + 3) * SWR + wk] = wv.w;                                      \
  }

    // thread z handles k-pairs kp = z + 8j (j=0..3) of each 64-k tile
#define COMPUTE_TILE(buf_)                                                   \
  { const float* _a = &sA[buf_][wid * 8 * SAR + 2 * z];                      \
    const float* _w = &sW[buf_][cg * 4 * SWR + 2 * z];                       \
    _Pragma("unroll")                                                        \
    for (int j = 0; j < 4; ++j) {                                            \
      ull Ar[8]; ull Wr[4];                                                  \
      _Pragma("unroll")                                                      \
      for (int r = 0; r < 8; ++r) Ar[r] = *(const ull*)(_a + r * SAR + 16 * j); \
      _Pragma("unroll")                                                      \
      for (int c = 0; c < 4; ++c) Wr[c] = *(const ull*)(_w + c * SWR + 16 * j); \
      _Pragma("unroll")                                                      \
      for (int r = 0; r < 8; ++r) {                                          \
        acc[r][0] = fma2(Ar[r], Wr[0], acc[r][0]);                           \
        acc[r][1] = fma2(Ar[r], Wr[1], acc[r][1]);                           \
        acc[r][2] = fma2(Ar[r], Wr[2], acc[r][2]);                           \
        acc[r][3] = fma2(Ar[r], Wr[3], acc[r][3]);                           \
      }                                                                      \
    } }

#define WAIT_CHUNK(c_, t_)                                                   \
  { if (tid == 0) {                                                          \
      const u32* _c = &g_cnt[mi][c_][0][0];                                  \
      for (;;) {                                                             \
        u32 _s = ldacq(_c) + ldacq(_c + 16) + ldacq(_c + 32) + ldacq(_c + 48); \
        if (_s >= 2048u * (u32)(t_) || bud <= 0) break;                      \
        __nanosleep(64); --bud;                                              \
      }                                                                      \
    }                                                                        \
    __syncthreads(); }

#pragma unroll 1
    for (int t = 0; t < TT; ++t) {
        ull acc[8][4];
#pragma unroll
        for (int r = 0; r < 8; ++r)
#pragma unroll
            for (int c = 0; c < 4; ++c) acc[r][c] = 0ull;

        const int ntiles = (t == 0) ? 4 : 20;   // x tiles 0..3, h tiles 4..19

        LDG_TILE(0, t);
#pragma unroll 1
        for (int kt = 0; kt < ntiles; ++kt) {
            STS_TILE(kt & 1);
            __syncthreads();
            if (kt + 1 < ntiles) {
                if (kt + 1 >= 4 && (((kt + 1) - 4) & 1) == 0)
                    WAIT_CHUNK(((kt + 1) - 4) >> 1, t);
                LDG_TILE(kt + 1, t);
            }
            COMPUTE_TILE(kt & 1);
            __syncthreads();
        }

        // ---- k-split reduction: butterfly over z (lane bits 0..2) ----
#pragma unroll
        for (int d = 1; d <= 4; d <<= 1) {
#pragma unroll
            for (int r = 0; r < 8; ++r)
#pragma unroll
                for (int c = 0; c < 4; ++c)
                    acc[r][c] = add2(acc[r][c],
                                     __shfl_xor_sync(0xFFFFFFFFu, acc[r][c], d));
        }

        // ---- epilogue: lane z stores row wid*8+z, cols n0+4cg..+3 ----
        {
            ull s0 = 0, s1 = 0, s2 = 0, s3 = 0;
#pragma unroll
            for (int r = 0; r < 8; ++r)
                if (z == r) { s0 = acc[r][0]; s1 = acc[r][1]; s2 = acc[r][2]; s3 = acc[r][3]; }
            float2 f0 = unp2(s0), f1 = unp2(s1), f2 = unp2(s2), f3 = unp2(s3);
            float v0 = tanhf(f0.x + f0.y + bias4.x);
            float v1 = tanhf(f1.x + f1.y + bias4.y);
            float v2 = tanhf(f2.x + f2.y + bias4.z);
            float v3 = tanhf(f3.x + f3.y + bias4.w);
            float* o = out + (size_t)t * (BB * LATN)
                           + (size_t)(m0 + wid * 8 + z) * LATN + n0 + 4 * cg;
            *(float4*)o = make_float4(v0, v1, v2, v3);
            // publish: release orders this thread's store before the count
            asm volatile("red.release.gpu.add.u32 [%0], %1;"
                         :: "l"(&g_cnt[mi][sub][tid & 3][0]), "r"(1u) : "memory");
        }
    }

    // ---- reset counters for next graph replay ----
    if (tid == 0 && (nj & 7) == 0) {
        u32* c = &g_cnt[mi][sub][0][0];
        for (;;) {
            u32 s = ldacq(c) + ldacq(c + 16) + ldacq(c + 32) + ldacq(c + 48);
            if (s >= 2048u * (u32)TT || bud <= 0) break;
            __nanosleep(64); --bud;
        }
        asm volatile("st.relaxed.gpu.u32 [%0], %1;" :: "l"(c),      "r"(0u) : "memory");
        asm volatile("st.relaxed.gpu.u32 [%0], %1;" :: "l"(c + 16), "r"(0u) : "memory");
        asm volatile("st.relaxed.gpu.u32 [%0], %1;" :: "l"(c + 32), "r"(0u) : "memory");
        asm volatile("st.relaxed.gpu.u32 [%0], %1;" :: "l"(c + 48), "r"(0u) : "memory");
    }
}

extern "C" void kernel_launch(void* const* d_in, const int* in_sizes, int n_in,
                              void* d_out, int out_size)
{
    const float* x = (const float*)d_in[0];   // (128, 512, 256) f32
    const float* W = (const float*)d_in[1];   // (1280, 1024) f32
    const float* b = (const float*)d_in[2];   // (1024,) f32
    float* out = (float*)d_out;               // (512, 128, 1024) f32

    rnn_persist<<<128, NT>>>(x, W, b, out);
}

// round 11
// speedup vs baseline: 1.3765x; 1.3765x over previous
#include <cuda_runtime.h>
#include <cstdint>

#define TT   512
#define BB   128
#define LATN 1024
#define DIMX 256
#define BM   64
#define BN   16
#define BK   64
#define SAR  68      // A-tile [m][k] row stride (mult of 4 -> STS.128 aligned)
#define SAW  66      // W-tile [n][k] row stride
#define NT   256

typedef unsigned long long ull;
typedef unsigned u32;

// publish counters: [mi][chunk][part][pad16] (64B apart)
__device__ u32 g_cnt[2][8][2][16];

__device__ __forceinline__ ull fma2(ull a, ull b, ull c) {
    ull d; asm("fma.rn.f32x2 %0, %1, %2, %3;" : "=l"(d) : "l"(a), "l"(b), "l"(c)); return d;
}
__device__ __forceinline__ ull add2(ull a, ull b) {
    ull d; asm("add.rn.f32x2 %0, %1, %2;" : "=l"(d) : "l"(a), "l"(b)); return d;
}
__device__ __forceinline__ float2 unp2(ull v) {
    float2 f; asm("mov.b64 {%0, %1}, %2;" : "=f"(f.x), "=f"(f.y) : "l"(v)); return f;
}
__device__ __forceinline__ u32 ldacq(const u32* p) {
    u32 v; asm volatile("ld.acquire.gpu.u32 %0, [%1];" : "=r"(v) : "l"(p) : "memory"); return v;
}

__global__ void __launch_bounds__(NT, 1)
rnn_persist(const float* __restrict__ x, const float* __restrict__ W,
            const float* __restrict__ b, float* __restrict__ out)
{
    __shared__ float sA[2][BM * SAR];   // 34816 B
    __shared__ float sWt[2][BN * SAW];  //  8448 B

    const int tid = threadIdx.x;
    const int cta = blockIdx.x;
    const int mi  = cta & 1;            // M-half
    const int nj  = cta >> 1;           // N-tile 0..63
    const int m0  = mi * BM;
    const int n0  = nj * BN;
    const int sub = nj >> 3;            // 128-col chunk this CTA produces

    const int z    = tid >> 7;          // k-split half of each tile
    const int t128 = tid & 127;
    const int tn   = t128 & 7;          // col pair: n0 + 2tn + {0,1}
    const int tm   = t128 >> 3;         // rows {tm, tm+16, tm+32, tm+48}

    const int lk4 = tid & 7;            // loader: k-quads {lk4, lk4+8}
    const int lm  = tid >> 3;           // loader: rows {lm, lm+32}

    const int wk = tid >> 2;            // w loader: k row 0..63
    const int wc = tid & 3;             // w loader: col quad

    const float b0 = b[n0 + 2 * tn];
    const float b1 = b[n0 + 2 * tn + 1];

    long long budget = 1LL << 22;

    float4 va0, va1, va2, va3, wv;

#define LDG_TILE(kt_, t_)                                                   \
  { const int _kt = (kt_);                                                  \
    wv = *(const float4*)(W + (size_t)(_kt * BK + wk) * LATN + n0 + 4 * wc);\
    if (_kt < 4) {                                                          \
      const float* _p = x + (size_t)(m0 + lm) * (TT * DIMX)                 \
                          + (size_t)(t_) * DIMX + _kt * BK + 4 * lk4;       \
      va0 = __ldcs((const float4*)(_p));                                    \
      va1 = __ldcs((const float4*)(_p + 32));                               \
      va2 = __ldcs((const float4*)(_p + 32 * (TT * DIMX)));                 \
      va3 = __ldcs((const float4*)(_p + 32 * (TT * DIMX) + 32));            \
    } else {                                                                \
      const float* _p = out + (size_t)((t_) - 1) * (BB * LATN)              \
                            + (size_t)(m0 + lm) * LATN                      \
                            + (_kt - 4) * BK + 4 * lk4;                     \
      va0 = __ldcs((const float4*)(_p));                                    \
      va1 = __ldcs((const float4*)(_p + 32));                               \
      va2 = __ldcs((const float4*)(_p + 32 * LATN));                        \
      va3 = __ldcs((const float4*)(_p + 32 * LATN + 32));                   \
    } }

#define STS_TILE(buf_)                                                      \
  { float* _a = &sA[buf_][0];                                               \
    *(float4*)(_a + lm * SAR + 4 * lk4)              = va0;                 \
    *(float4*)(_a + lm * SAR + 4 * lk4 + 32)         = va1;                 \
    *(float4*)(_a + (lm + 32) * SAR + 4 * lk4)       = va2;                 \
    *(float4*)(_a + (lm + 32) * SAR + 4 * lk4 + 32)  = va3;                 \
    float* _w = &sWt[buf_][0];                                              \
    _w[(4 * wc + 0) * SAW + wk] = wv.x;                                     \
    _w[(4 * wc + 1) * SAW + wk] = wv.y;                                     \
    _w[(4 * wc + 2) * SAW + wk] = wv.z;                                     \
    _w[(4 * wc + 3) * SAW + wk] = wv.w;                                     \
  }

    // k-pair accumulation; rows strided by 16 -> banks 4*tm mod 32: conflict-free
#define COMPUTE_TILE(buf_)                                                  \
  { const float* _a = &sA[buf_][tm * SAR + z * 32];                         \
    const float* _w = &sWt[buf_][2 * tn * SAW + z * 32];                    \
    _Pragma("unroll")                                                       \
    for (int kp = 0; kp < 16; ++kp) {                                       \
      ull A0 = *(const ull*)(_a + 2 * kp);                                  \
      ull A1 = *(const ull*)(_a + 16 * SAR + 2 * kp);                       \
      ull A2 = *(const ull*)(_a + 32 * SAR + 2 * kp);                       \
      ull A3 = *(const ull*)(_a + 48 * SAR + 2 * kp);                       \
      ull W0 = *(const ull*)(_w + 2 * kp);                                  \
      ull W1 = *(const ull*)(_w + SAW + 2 * kp);                            \
      ac00 = fma2(A0, W0, ac00);  ac01 = fma2(A0, W1, ac01);                \
      ac10 = fma2(A1, W0, ac10);  ac11 = fma2(A1, W1, ac11);                \
      ac20 = fma2(A2, W0, ac20);  ac21 = fma2(A2, W1, ac21);                \
      ac30 = fma2(A3, W0, ac30);  ac31 = fma2(A3, W1, ac31);                \
    } }

#define WAIT_SUB(s_, tgt_)                                                  \
  { if (tid == 0) {                                                         \
      const u32* _c = &g_cnt[mi][s_][0][0];                                 \
      for (;;) {                                                            \
        u32 _v = ldacq(_c) + ldacq(_c + 16);                                \
        if (_v >= (u32)(tgt_) || budget <= 0) break;                        \
        __nanosleep(64); --budget;                                          \
      }                                                                     \
    }                                                                       \
    __syncthreads(); }

#pragma unroll 1
    for (int t = 0; t < TT; ++t) {
        ull ac00 = 0, ac01 = 0, ac10 = 0, ac11 = 0;
        ull ac20 = 0, ac21 = 0, ac30 = 0, ac31 = 0;

        const int ntiles = (t == 0) ? 4 : 20;   // x tiles 0..3, h tiles 4..19

        LDG_TILE(0, t);
#pragma unroll 1
        for (int kt = 0; kt < ntiles; ++kt) {
            STS_TILE(kt & 1);
            __syncthreads();
            if (kt + 1 < ntiles) {
                if (kt + 1 >= 4 && (((kt + 1) - 4) & 1) == 0)
                    WAIT_SUB(((kt + 1) - 4) >> 1, 1024u * (u32)t);
                LDG_TILE(kt + 1, t);
            }
            COMPUTE_TILE(kt & 1);
        }

        // ---- reduce the two z-halves via smem scratch ----
        ull* red = (ull*)&sA[0][0];
        __syncthreads();
        if (z == 1) {
            red[t128 * 8 + 0] = ac00;  red[t128 * 8 + 1] = ac01;
            red[t128 * 8 + 2] = ac10;  red[t128 * 8 + 3] = ac11;
            red[t128 * 8 + 4] = ac20;  red[t128 * 8 + 5] = ac21;
            red[t128 * 8 + 6] = ac30;  red[t128 * 8 + 7] = ac31;
        }
        __syncthreads();
        if (z == 0) {
            ac00 = add2(ac00, red[t128 * 8 + 0]);  ac01 = add2(ac01, red[t128 * 8 + 1]);
            ac10 = add2(ac10, red[t128 * 8 + 2]);  ac11 = add2(ac11, red[t128 * 8 + 3]);
            ac20 = add2(ac20, red[t128 * 8 + 4]);  ac21 = add2(ac21, red[t128 * 8 + 5]);
            ac30 = add2(ac30, red[t128 * 8 + 6]);  ac31 = add2(ac31, red[t128 * 8 + 7]);

            float2 r;
            float* o = out + (size_t)t * (BB * LATN)
                           + (size_t)(m0 + tm) * LATN + n0 + 2 * tn;
            r = unp2(ac00); float v00 = r.x + r.y + b0;
            r = unp2(ac01); float v01 = r.x + r.y + b1;
            r = unp2(ac10); float v10 = r.x + r.y + b0;
            r = unp2(ac11); float v11 = r.x + r.y + b1;
            r = unp2(ac20); float v20 = r.x + r.y + b0;
            r = unp2(ac21); float v21 = r.x + r.y + b1;
            r = unp2(ac30); float v30 = r.x + r.y + b0;
            r = unp2(ac31); float v31 = r.x + r.y + b1;
            *(float2*)(o)             = make_float2(tanhf(v00), tanhf(v01));
            *(float2*)(o + 16 * LATN) = make_float2(tanhf(v10), tanhf(v11));
            *(float2*)(o + 32 * LATN) = make_float2(tanhf(v20), tanhf(v21));
            *(float2*)(o + 48 * LATN) = make_float2(tanhf(v30), tanhf(v31));

            // publish: per-thread release orders this thread's stores before count
            // (no __threadfence -> no L1D flush -> W stays L1-resident)
            asm volatile("red.release.gpu.add.u32 [%0], %1;"
                         :: "l"(&g_cnt[mi][sub][t128 & 1][0]), "r"(1u) : "memory");
        }
        __syncthreads();   // protect red scratch before next step's STS_TILE(0)
    }

    // ---- reset counters for next graph replay (one resetter per chunk) ----
    if (tid == 0 && (nj & 7) == 0) {
        u32* c = &g_cnt[mi][sub][0][0];
        for (;;) {
            u32 v = ldacq(c) + ldacq(c + 16);
            if (v >= 1024u * (u32)TT || budget <= 0) break;
            __nanosleep(64); --budget;
        }
        asm volatile("st.relaxed.gpu.u32 [%0], %1;" :: "l"(c),      "r"(0u) : "memory");
        asm volatile("st.relaxed.gpu.u32 [%0], %1;" :: "l"(c + 16), "r"(0u) : "memory");
    }
}

extern "C" void kernel_launch(void* const* d_in, const int* in_sizes, int n_in,
                              void* d_out, int out_size)
{
    const float* x = (const float*)d_in[0];   // (128, 512, 256) f32
    const float* W = (const float*)d_in[1];   // (1280, 1024) f32
    const float* b = (const float*)d_in[2];   // (1024,) f32
    float* out = (float*)d_out;               // (512, 128, 1024) f32

    rnn_persist<<<128, NT>>>(x, W, b, out);
}

// round 12
// speedup vs baseline: 1.5037x; 1.0924x over previous
#include <cuda_runtime.h>
#include <cstdint>

#define TT   512
#define BB   128
#define LATN 1024
#define DIMX 256
#define BM   64
#define BN   16
#define BK   128
#define SAR  132     // A-tile [m][k] row stride (mult of 4 for STS.128)
#define SAW  130     // W-tile [n][k] row stride (2tn*130 mod 32 = 4tn -> conflict-free)
#define NT   256
#define NXT  2       // x tiles (256 k)
#define NHT  8       // h tiles (1024 k)

typedef unsigned long long ull;
typedef unsigned u32;

// publish counters: [mi][chunk][pad32] (128B apart)
__device__ u32 g_cnt[2][8][32];

__device__ __forceinline__ ull fma2(ull a, ull b, ull c) {
    ull d; asm("fma.rn.f32x2 %0, %1, %2, %3;" : "=l"(d) : "l"(a), "l"(b), "l"(c)); return d;
}
__device__ __forceinline__ ull add2(ull a, ull b) {
    ull d; asm("add.rn.f32x2 %0, %1, %2;" : "=l"(d) : "l"(a), "l"(b)); return d;
}
__device__ __forceinline__ float2 unp2(ull v) {
    float2 f; asm("mov.b64 {%0, %1}, %2;" : "=f"(f.x), "=f"(f.y) : "l"(v)); return f;
}
__device__ __forceinline__ u32 ldacq(const u32* p) {
    u32 v; asm volatile("ld.acquire.gpu.u32 %0, [%1];" : "=r"(v) : "l"(p) : "memory"); return v;
}

#define SA_FLOATS (BM * SAR)          // 8448
#define SW_FLOATS (BN * SAW)          // 2080
#define SMEM_BYTES ((2 * SA_FLOATS + 2 * SW_FLOATS) * 4)   // 84224

__global__ void __launch_bounds__(NT, 1)
rnn_persist(const float* __restrict__ x, const float* __restrict__ W,
            const float* __restrict__ b, float* __restrict__ out)
{
    extern __shared__ float sm[];
    float* sA0 = sm;                          // buf0 A
    float* sA1 = sm + SA_FLOATS;              // buf1 A
    float* sW0 = sm + 2 * SA_FLOATS;          // buf0 W
    float* sW1 = sm + 2 * SA_FLOATS + SW_FLOATS;

    const int tid = threadIdx.x;
    const int cta = blockIdx.x;
    const int mi  = cta & 1;            // M-half
    const int nj  = cta >> 1;           // N-tile 0..63
    const int m0  = mi * BM;
    const int n0  = nj * BN;
    const int sub = nj >> 3;            // 128-col chunk this CTA produces

    const int z    = tid >> 7;          // k-split half of each tile
    const int t128 = tid & 127;
    const int tn   = t128 & 7;          // col pair: n0 + 2tn + {0,1}
    const int tm   = t128 >> 3;         // row quad: 4tm .. 4tm+3

    const int lm  = tid >> 5;           // a loader: rows lm + 8i, i<8
    const int lk4 = tid & 31;           // a loader: k-quad
    const int wk  = tid >> 2;           // w loader: k rows {wk, wk+64}
    const int wc  = tid & 3;            // w loader: col quad

    const float b0 = b[n0 + 2 * tn];
    const float b1 = b[n0 + 2 * tn + 1];

    long long budget = 1LL << 22;       // bounded spins

    float4 va[8], wv[2];

#define LDG_TILE(kt_, t_)                                                    \
  { const int _kt = (kt_);                                                   \
    wv[0] = *(const float4*)(W + (size_t)(_kt * BK + wk) * LATN + n0 + 4 * wc);      \
    wv[1] = *(const float4*)(W + (size_t)(_kt * BK + wk + 64) * LATN + n0 + 4 * wc); \
    if (_kt < NXT) {                                                         \
      const float* _p = x + (size_t)(m0 + lm) * (TT * DIMX)                  \
                          + (size_t)(t_) * DIMX + _kt * BK + 4 * lk4;        \
      _Pragma("unroll")                                                      \
      for (int i = 0; i < 8; ++i)                                            \
        va[i] = *(const float4*)(_p + (size_t)(8 * i) * (TT * DIMX));        \
    } else {                                                                 \
      const float* _p = out + (size_t)((t_) - 1) * (BB * LATN)               \
                            + (size_t)(m0 + lm) * LATN                       \
                            + (_kt - NXT) * BK + 4 * lk4;                    \
      _Pragma("unroll")                                                      \
      for (int i = 0; i < 8; ++i)                                            \
        va[i] = *(const float4*)(_p + (size_t)(8 * i) * LATN);               \
    } }

#define STS_TILE(buf_)                                                      \
  { float* _a = (buf_) ? sA1 : sA0;                                         \
    _Pragma("unroll")                                                       \
    for (int i = 0; i < 8; ++i)                                             \
      *(float4*)(_a + (lm + 8 * i) * SAR + 4 * lk4) = va[i];                \
    float* _w = (buf_) ? sW1 : sW0;                                         \
    _w[(4 * wc + 0) * SAW + wk] = wv[0].x;                                  \
    _w[(4 * wc + 1) * SAW + wk] = wv[0].y;                                  \
    _w[(4 * wc + 2) * SAW + wk] = wv[0].z;                                  \
    _w[(4 * wc + 3) * SAW + wk] = wv[0].w;                                  \
    _w[(4 * wc + 0) * SAW + wk + 64] = wv[1].x;                             \
    _w[(4 * wc + 1) * SAW + wk + 64] = wv[1].y;                             \
    _w[(4 * wc + 2) * SAW + wk + 64] = wv[1].z;                             \
    _w[(4 * wc + 3) * SAW + wk + 64] = wv[1].w;                             \
  }

    // k-pair accumulation over this thread's 64-k half of the 128-k tile
#define COMPUTE_TILE(buf_)                                                  \
  { const float* _a = ((buf_) ? sA1 : sA0) + 4 * tm * SAR + z * 64;         \
    const float* _w = ((buf_) ? sW1 : sW0) + 2 * tn * SAW + z * 64;         \
    _Pragma("unroll")                                                       \
    for (int kp = 0; kp < 32; ++kp) {                                       \
      ull A0 = *(const ull*)(_a + 2 * kp);                                  \
      ull A1 = *(const ull*)(_a + SAR + 2 * kp);                            \
      ull A2 = *(const ull*)(_a + 2 * SAR + 2 * kp);                        \
      ull A3 = *(const ull*)(_a + 3 * SAR + 2 * kp);                        \
      ull W0 = *(const ull*)(_w + 2 * kp);                                  \
      ull W1 = *(const ull*)(_w + SAW + 2 * kp);                            \
      ac00 = fma2(A0, W0, ac00);  ac01 = fma2(A0, W1, ac01);                \
      ac10 = fma2(A1, W0, ac10);  ac11 = fma2(A1, W1, ac11);                \
      ac20 = fma2(A2, W0, ac20);  ac21 = fma2(A2, W1, ac21);                \
      ac30 = fma2(A3, W0, ac30);  ac31 = fma2(A3, W1, ac31);                \
    } }

#define WAIT_SUB(s_, tgt_)                                                  \
  { if (tid == 0) {                                                         \
      const u32* _c = &g_cnt[mi][s_][0];                                    \
      for (;;) {                                                            \
        u32 _v = ldacq(_c);                                                 \
        if (_v >= (u32)(tgt_) || budget <= 0) break;                        \
        __nanosleep(64); --budget;                                          \
      }                                                                     \
    }                                                                       \
    __syncthreads(); }

#pragma unroll 1
    for (int t = 0; t < TT; ++t) {
        ull ac00 = 0, ac01 = 0, ac10 = 0, ac11 = 0;
        ull ac20 = 0, ac21 = 0, ac30 = 0, ac31 = 0;

        const int ntiles = (t == 0) ? NXT : (NXT + NHT);   // 2 or 10

        LDG_TILE(0, t);
#pragma unroll 1
        for (int kt = 0; kt < ntiles; ++kt) {
            STS_TILE(kt & 1);
            __syncthreads();
            if (kt + 1 < ntiles) {
                if (kt + 1 >= NXT)
                    WAIT_SUB((kt + 1) - NXT, 8u * (u32)t);
                LDG_TILE(kt + 1, t);
            }
            COMPUTE_TILE(kt & 1);
        }

        // ---- reduce the two z-halves via smem scratch (buf0 A region) ----
        ull* red = (ull*)sA0;
        __syncthreads();
        if (z == 1) {
            red[t128 * 8 + 0] = ac00;  red[t128 * 8 + 1] = ac01;
            red[t128 * 8 + 2] = ac10;  red[t128 * 8 + 3] = ac11;
            red[t128 * 8 + 4] = ac20;  red[t128 * 8 + 5] = ac21;
            red[t128 * 8 + 6] = ac30;  red[t128 * 8 + 7] = ac31;
        }
        __syncthreads();
        if (z == 0) {
            ac00 = add2(ac00, red[t128 * 8 + 0]);  ac01 = add2(ac01, red[t128 * 8 + 1]);
            ac10 = add2(ac10, red[t128 * 8 + 2]);  ac11 = add2(ac11, red[t128 * 8 + 3]);
            ac20 = add2(ac20, red[t128 * 8 + 4]);  ac21 = add2(ac21, red[t128 * 8 + 5]);
            ac30 = add2(ac30, red[t128 * 8 + 6]);  ac31 = add2(ac31, red[t128 * 8 + 7]);

            float2 r;
            float* o = out + (size_t)t * (BB * LATN)
                           + (size_t)(m0 + 4 * tm) * LATN + n0 + 2 * tn;
            r = unp2(ac00); float v00 = r.x + r.y + b0;
            r = unp2(ac01); float v01 = r.x + r.y + b1;
            r = unp2(ac10); float v10 = r.x + r.y + b0;
            r = unp2(ac11); float v11 = r.x + r.y + b1;
            r = unp2(ac20); float v20 = r.x + r.y + b0;
            r = unp2(ac21); float v21 = r.x + r.y + b1;
            r = unp2(ac30); float v30 = r.x + r.y + b0;
            r = unp2(ac31); float v31 = r.x + r.y + b1;
            *(float2*)(o)            = make_float2(tanhf(v00), tanhf(v01));
            *(float2*)(o + LATN)     = make_float2(tanhf(v10), tanhf(v11));
            *(float2*)(o + 2 * LATN) = make_float2(tanhf(v20), tanhf(v21));
            *(float2*)(o + 3 * LATN) = make_float2(tanhf(v30), tanhf(v31));
        }

        // ---- publish h_t (round-3 protocol) ----
        __threadfence();
        __syncthreads();
        if (tid == 0) atomicAdd(&g_cnt[mi][sub][0], 1u);
    }

    // ---- reset counters for next graph replay (one resetter per chunk) ----
    if (tid == 0 && (nj & 7) == 0) {
        u32* c = &g_cnt[mi][sub][0];
        for (;;) {
            u32 v = ldacq(c);
            if (v >= 8u * (u32)TT || budget <= 0) break;
            __nanosleep(64); --budget;
        }
        asm volatile("st.relaxed.gpu.u32 [%0], %1;" :: "l"(c), "r"(0u) : "memory");
    }
}

extern "C" void kernel_launch(void* const* d_in, const int* in_sizes, int n_in,
                              void* d_out, int out_size)
{
    const float* x = (const float*)d_in[0];   // (128, 512, 256) f32
    const float* W = (const float*)d_in[1];   // (1280, 1024) f32
    const float* b = (const float*)d_in[2];   // (1024,) f32
    float* out = (float*)d_out;               // (512, 128, 1024) f32

    cudaFuncSetAttribute(rnn_persist,
                         cudaFuncAttributeMaxDynamicSharedMemorySize, SMEM_BYTES);
    rnn_persist<<<128, NT, SMEM_BYTES>>>(x, W, b, out);
}

// round 15
// speedup vs baseline: 1.5975x; 1.0624x over previous
#include <cuda_runtime.h>
#include <cstdint>

#define TT   512
#define BB   128
#define LATN 1024
#define DIMX 256
#define BM   64
#define BN   16
#define BK   128
#define SAR  132     // A-tile [m][k] row stride
#define SAW  130     // W-tile [n][k] row stride
#define NT   256
#define NXT  2       // x tiles (256 k)
#define NHT  8       // h tiles (1024 k)

typedef unsigned long long ull;
typedef unsigned u32;

// publish counters: [mi][chunk][pad32] (128B apart)
__device__ u32 g_cnt[2][8][32];

__device__ __forceinline__ ull fma2(ull a, ull b, ull c) {
    ull d; asm("fma.rn.f32x2 %0, %1, %2, %3;" : "=l"(d) : "l"(a), "l"(b), "l"(c)); return d;
}
__device__ __forceinline__ ull add2(ull a, ull b) {
    ull d; asm("add.rn.f32x2 %0, %1, %2;" : "=l"(d) : "l"(a), "l"(b)); return d;
}
__device__ __forceinline__ float2 unp2(ull v) {
    float2 f; asm("mov.b64 {%0, %1}, %2;" : "=f"(f.x), "=f"(f.y) : "l"(v)); return f;
}
__device__ __forceinline__ u32 ldacq(const u32* p) {
    u32 v; asm volatile("ld.acquire.gpu.u32 %0, [%1];" : "=r"(v) : "l"(p) : "memory"); return v;
}

#define SA_FLOATS (BM * SAR)          // 8448
#define SW_FLOATS (BN * SAW)          // 2080
#define SMEM_BYTES ((2 * SA_FLOATS + 2 * SW_FLOATS) * 4)   // 84224

__global__ void __launch_bounds__(NT, 1)
rnn_persist(const float* __restrict__ x, const float* __restrict__ W,
            const float* __restrict__ b, float* __restrict__ out)
{
    extern __shared__ float sm[];
    float* sA0 = sm;
    float* sA1 = sm + SA_FLOATS;
    float* sW0 = sm + 2 * SA_FLOATS;
    float* sW1 = sm + 2 * SA_FLOATS + SW_FLOATS;

    const int tid = threadIdx.x;
    const int cta = blockIdx.x;
    const int mi  = cta & 1;            // M-half
    const int nj  = cta >> 1;           // N-tile 0..63
    const int m0  = mi * BM;
    const int n0  = nj * BN;
    const int sub = nj >> 3;            // 128-col chunk this CTA produces

    const int lane = tid & 31;
    const int w    = tid >> 5;          // warp 0..7
    const int z    = lane >> 3;         // 4-way k-split (lane bits 3,4)
    const int c    = lane & 3;          // col group: cols n0 + 4c .. +3
    const int r    = 2 * w + ((lane >> 2) & 1);   // row group: rows 4r..4r+3

    const int lm  = tid >> 5;           // a loader: rows lm + 8i, i<8
    const int lk4 = tid & 31;           // a loader: k-quad
    const int wk  = tid >> 2;           // w loader: k rows {wk, wk+64}
    const int wc  = tid & 3;            // w loader: col quad

    const float4 bias4 = *(const float4*)(b + n0 + 4 * c);

    long long budget = 1LL << 22;       // bounded spins

    float4 va[8], wv[2];

#define LDG_TILE(kt_, t_)                                                    \
  { const int _kt = (kt_);                                                   \
    wv[0] = *(const float4*)(W + (size_t)(_kt * BK + wk) * LATN + n0 + 4 * wc);      \
    wv[1] = *(const float4*)(W + (size_t)(_kt * BK + wk + 64) * LATN + n0 + 4 * wc); \
    if (_kt < NXT) {                                                         \
      const float* _p = x + (size_t)(m0 + lm) * (TT * DIMX)                  \
                          + (size_t)(t_) * DIMX + _kt * BK + 4 * lk4;        \
      _Pragma("unroll")                                                      \
      for (int i = 0; i < 8; ++i)                                            \
        va[i] = *(const float4*)(_p + (size_t)(8 * i) * (TT * DIMX));        \
    } else {                                                                 \
      const float* _p = out + (size_t)((t_) - 1) * (BB * LATN)               \
                            + (size_t)(m0 + lm) * LATN                       \
                            + (_kt - NXT) * BK + 4 * lk4;                    \
      _Pragma("unroll")                                                      \
      for (int i = 0; i < 8; ++i)                                            \
        va[i] = *(const float4*)(_p + (size_t)(8 * i) * LATN);               \
    } }

#define STS_TILE(buf_)                                                      \
  { float* _a = (buf_) ? sA1 : sA0;                                         \
    _Pragma("unroll")                                                       \
    for (int i = 0; i < 8; ++i)                                             \
      *(float4*)(_a + (lm + 8 * i) * SAR + 4 * lk4) = va[i];                \
    float* _w = (buf_) ? sW1 : sW0;                                         \
    _w[(4 * wc + 0) * SAW + wk] = wv[0].x;                                  \
    _w[(4 * wc + 1) * SAW + wk] = wv[0].y;                                  \
    _w[(4 * wc + 2) * SAW + wk] = wv[0].z;                                  \
    _w[(4 * wc + 3) * SAW + wk] = wv[0].w;                                  \
    _w[(4 * wc + 0) * SAW + wk + 64] = wv[1].x;                             \
    _w[(4 * wc + 1) * SAW + wk + 64] = wv[1].y;                             \
    _w[(4 * wc + 2) * SAW + wk + 64] = wv[1].z;                             \
    _w[(4 * wc + 3) * SAW + wk + 64] = wv[1].w;                             \
  }

    // k-pairs of tile: p = 4j + z (j = 0..15); acc = (even-k sum, odd-k sum)
#define COMPUTE_TILE(buf_)                                                  \
  { const float* _a = ((buf_) ? sA1 : sA0) + 4 * r * SAR + 2 * z;           \
    const float* _w = ((buf_) ? sW1 : sW0) + 4 * c * SAW + 2 * z;           \
    _Pragma("unroll")                                                       \
    for (int j = 0; j < 16; ++j) {                                          \
      ull A0 = *(const ull*)(_a + 8 * j);                                   \
      ull A1 = *(const ull*)(_a + SAR + 8 * j);                             \
      ull A2 = *(const ull*)(_a + 2 * SAR + 8 * j);                         \
      ull A3 = *(const ull*)(_a + 3 * SAR + 8 * j);                         \
      ull W0 = *(const ull*)(_w + 8 * j);                                   \
      ull W1 = *(const ull*)(_w + SAW + 8 * j);                             \
      ull W2 = *(const ull*)(_w + 2 * SAW + 8 * j);                         \
      ull W3 = *(const ull*)(_w + 3 * SAW + 8 * j);                         \
      ac[0][0] = fma2(A0, W0, ac[0][0]);  ac[0][1] = fma2(A0, W1, ac[0][1]);\
      ac[0][2] = fma2(A0, W2, ac[0][2]);  ac[0][3] = fma2(A0, W3, ac[0][3]);\
      ac[1][0] = fma2(A1, W0, ac[1][0]);  ac[1][1] = fma2(A1, W1, ac[1][1]);\
      ac[1][2] = fma2(A1, W2, ac[1][2]);  ac[1][3] = fma2(A1, W3, ac[1][3]);\
      ac[2][0] = fma2(A2, W0, ac[2][0]);  ac[2][1] = fma2(A2, W1, ac[2][1]);\
      ac[2][2] = fma2(A2, W2, ac[2][2]);  ac[2][3] = fma2(A2, W3, ac[2][3]);\
      ac[3][0] = fma2(A3, W0, ac[3][0]);  ac[3][1] = fma2(A3, W1, ac[3][1]);\
      ac[3][2] = fma2(A3, W2, ac[3][2]);  ac[3][3] = fma2(A3, W3, ac[3][3]);\
    } }

#define WAIT_SUB(s_, tgt_)                                                  \
  { if (tid == 0) {                                                         \
      const u32* _c = &g_cnt[mi][s_][0];                                    \
      for (;;) {                                                            \
        u32 _v = ldacq(_c);                                                 \
        if (_v >= (u32)(tgt_) || budget <= 0) break;                        \
        __nanosleep(64); --budget;                                          \
      }                                                                     \
    }                                                                       \
    __syncthreads(); }

#pragma unroll 1
    for (int t = 0; t < TT; ++t) {
        ull ac[4][4];
#pragma unroll
        for (int i = 0; i < 4; ++i)
#pragma unroll
            for (int m = 0; m < 4; ++m) ac[i][m] = 0ull;

        const int ntiles = (t == 0) ? NXT : (NXT + NHT);   // 2 or 10

        LDG_TILE(0, t);
#pragma unroll 1
        for (int kt = 0; kt < ntiles; ++kt) {
            STS_TILE(kt & 1);
            __syncthreads();
            if (kt + 1 < ntiles) {
                if (kt + 1 >= NXT)
                    WAIT_SUB((kt + 1) - NXT, 8u * (u32)t);
                LDG_TILE(kt + 1, t);
            }
            COMPUTE_TILE(kt & 1);
        }

        // ---- 4-way k-split reduction: shfl butterfly over lane bits 3,4 ----
#pragma unroll
        for (int d = 8; d <= 16; d <<= 1)
#pragma unroll
            for (int i = 0; i < 4; ++i)
#pragma unroll
                for (int m = 0; m < 4; ++m)
                    ac[i][m] = add2(ac[i][m],
                                    __shfl_xor_sync(0xFFFFFFFFu, ac[i][m], d));

        // ---- epilogue: lane (r,c,z) stores row 4r+z, cols n0+4c..+3 ----
        {
            float2 f0 = unp2(ac[z][0]);
            float2 f1 = unp2(ac[z][1]);
            float2 f2 = unp2(ac[z][2]);
            float2 f3 = unp2(ac[z][3]);
            float v0 = tanhf(f0.x + f0.y + bias4.x);
            float v1 = tanhf(f1.x + f1.y + bias4.y);
            float v2 = tanhf(f2.x + f2.y + bias4.z);
            float v3 = tanhf(f3.x + f3.y + bias4.w);
            float* o = out + (size_t)t * (BB * LATN)
                           + (size_t)(m0 + 4 * r + z) * LATN + n0 + 4 * c;
            *(float4*)o = make_float4(v0, v1, v2, v3);
        }

        // ---- publish h_t (proven protocol) ----
        __threadfence();
        __syncthreads();
        if (tid == 0) atomicAdd(&g_cnt[mi][sub][0], 1u);
    }

    // ---- reset counters for next graph replay (one resetter per chunk) ----
    if (tid == 0 && (nj & 7) == 0) {
        u32* cc = &g_cnt[mi][sub][0];
        for (;;) {
            u32 v = ldacq(cc);
            if (v >= 8u * (u32)TT || budget <= 0) break;
            __nanosleep(64); --budget;
        }
        asm volatile("st.relaxed.gpu.u32 [%0], %1;" :: "l"(cc), "r"(0u) : "memory");
    }
}

extern "C" void kernel_launch(void* const* d_in, const int* in_sizes, int n_in,
                              void* d_out, int out_size)
{
    const float* x = (const float*)d_in[0];   // (128, 512, 256) f32
    const float* W = (const float*)d_in[1];   // (1280, 1024) f32
    const float* b = (const float*)d_in[2];   // (1024,) f32
    float* out = (float*)d_out;               // (512, 128, 1024) f32

    cudaFuncSetAttribute(rnn_persist,
                         cudaFuncAttributeMaxDynamicSharedMemorySize, SMEM_BYTES);
    rnn_persist<<<128, NT, SMEM_BYTES>>>(x, W, b, out);
}